// round 6
// baseline (speedup 1.0000x reference)
#include <cuda_runtime.h>

#define N     8192
#define D     256
#define D4    64            // D/4
#define NCLS  10
#define NB    256           // blocks
#define RPB   32            // rows per block
#define SG    4             // subgroups (64 threads each)
#define RPSG  8             // rows per subgroup
#define SDIM  (NCLS * D)    // 2560
#define SDIM4 (NCLS * D4)   // 640

// Accumulators. Zero at module load; the last block re-zeroes them after the
// epilogue -> graph-replay safe, no separate zeroing kernel, no allocation.
__device__ float g_S[SDIM];
__device__ float g_Q[NCLS];
__device__ int   g_C[NCLS];
__device__ int   g_ctr;

__device__ __forceinline__ double block_reduce(double v, double* red, int t) {
    __syncthreads();
    red[t] = v;
    __syncthreads();
    #pragma unroll
    for (int s2 = 128; s2; s2 >>= 1) {
        if (t < s2) red[t] += red[t + s2];
        __syncthreads();
    }
    return red[0];
}

// ---------------------------------------------------------------------------
// Single kernel: stream 8 MB input -> per-class register accumulators
// (warp-uniform branch tree, one class body per row) -> shared merge ->
// global atomicAdd into g_S/g_Q/g_C -> last block runs epilogue + re-zero.
// ---------------------------------------------------------------------------
__global__ void __launch_bounds__(256) k_all(const float* __restrict__ x,
                                             const int* __restrict__ lab,
                                             float* __restrict__ res) {
    __shared__ float4 Ssh[SG][SDIM4];    // 40 KB: one buffer per subgroup
    __shared__ float  qred[8][NCLS];
    __shared__ int    labs[RPB];

    const int tid = threadIdx.x;
    const int g   = tid >> 6;            // subgroup 0..3
    const int t   = tid & 63;            // dim-group 0..63
    const int b   = blockIdx.x;

    if (tid < RPB) labs[tid] = lab[b * RPB + tid];
    __syncthreads();

    float4 S[NCLS];
    float  Q[NCLS];
    #pragma unroll
    for (int k = 0; k < NCLS; k++) {
        S[k] = make_float4(0.f, 0.f, 0.f, 0.f);
        Q[k] = 0.f;
    }

    const float4* __restrict__ p =
        reinterpret_cast<const float4*>(x) + (size_t)(b * RPB + g * RPSG) * D4 + t;

    // Front-batch all 8 row-loads (high MLP), then branch per row on the
    // subgroup-uniform label (no divergence, one class body per row).
    float4 v[RPSG];
    #pragma unroll
    for (int r = 0; r < RPSG; r++) v[r] = p[r * D4];

#define BODY(k) { S[k].x += v[r].x; S[k].y += v[r].y;                          \
                  S[k].z += v[r].z; S[k].w += v[r].w; Q[k] += q; }
    #pragma unroll
    for (int r = 0; r < RPSG; r++) {
        const int l = labs[g * RPSG + r];
        float q = v[r].x * v[r].x;
        q = fmaf(v[r].y, v[r].y, q);
        q = fmaf(v[r].z, v[r].z, q);
        q = fmaf(v[r].w, v[r].w, q);
        if      (l == 0) BODY(0)
        else if (l == 1) BODY(1)
        else if (l == 2) BODY(2)
        else if (l == 3) BODY(3)
        else if (l == 4) BODY(4)
        else if (l == 5) BODY(5)
        else if (l == 6) BODY(6)
        else if (l == 7) BODY(7)
        else if (l == 8) BODY(8)
        else             BODY(9)
    }
#undef BODY

    // Subgroups dump to private buffers (parallel, conflict-free).
    #pragma unroll
    for (int k = 0; k < NCLS; k++) Ssh[g][k * D4 + t] = S[k];
    __syncthreads();

    // Cooperative merge of the 4 buffers -> atomicAdd into global g_S.
    #pragma unroll
    for (int i = tid; i < SDIM4; i += 256) {
        float4 a = Ssh[0][i], b1 = Ssh[1][i], c = Ssh[2][i], d = Ssh[3][i];
        a.x += b1.x; a.y += b1.y; a.z += b1.z; a.w += b1.w;
        c.x += d.x;  c.y += d.y;  c.z += d.z;  c.w += d.w;
        a.x += c.x;  a.y += c.y;  a.z += c.z;  a.w += c.w;
        float* dst = &g_S[i * 4];
        atomicAdd(dst + 0, a.x);
        atomicAdd(dst + 1, a.y);
        atomicAdd(dst + 2, a.z);
        atomicAdd(dst + 3, a.w);
    }

    // Q: shfl-reduce each warp, then threads 0..9 sum 8 warps -> one atomic.
    const int lane = tid & 31, w = tid >> 5;
    #pragma unroll
    for (int k = 0; k < NCLS; k++) {
        float vq = Q[k];
        #pragma unroll
        for (int off = 16; off; off >>= 1)
            vq += __shfl_down_sync(0xffffffffu, vq, off);
        if (lane == 0) qred[w][k] = vq;
    }
    __syncthreads();
    if (tid < NCLS) {
        float s = 0.f;
        #pragma unroll
        for (int w2 = 0; w2 < 8; w2++) s += qred[w2][tid];
        atomicAdd(&g_Q[tid], s);
    }

    // Class counts: one warp ballots the 32 cached labels -> 10 int atomics.
    if (tid < 32) {
        int l = labs[tid];
        #pragma unroll
        for (int k = 0; k < NCLS; k++) {
            unsigned m = __ballot_sync(0xffffffffu, l == k);
            if (tid == 0 && m) atomicAdd(&g_C[k], (int)__popc(m));
        }
    }

    // ---- Last-block election ----
    __shared__ int isLast;
    __threadfence();
    __syncthreads();
    if (tid == 0) {
        int prev = atomicAdd(&g_ctr, 1);
        isLast = (prev == NB - 1) ? 1 : 0;
    }
    __syncthreads();
    if (!isLast) return;
    __threadfence();   // acquire: make all peers' atomics visible

    // ---------------- Epilogue (thread t2 = dim t2) ------------------------
    __shared__ double red[256];
    __shared__ float  Qs[NCLS];
    __shared__ int    Cs[NCLS];

    const int t2 = tid;
    if (t2 < NCLS) { Qs[t2] = g_Q[t2]; Cs[t2] = g_C[t2]; }
    const int firstL = lab[0];
    const int lastL  = lab[N - 1];
    const float v0 = x[t2];
    const float vN = x[(size_t)(N - 1) * D + t2];
    __syncthreads();

    double dsame = 0.0;
    float satot = 0.f, sbtot = 0.f;
    #pragma unroll
    for (int l = 0; l < NCLS; l++) {
        float sv = g_S[l * D + t2];
        float sa = sv - ((l == lastL)  ? vN : 0.f);   // rows i in [0, N-1)
        float sb = sv - ((l == firstL) ? v0 : 0.f);   // cols j in [1, N)
        dsame += (double)sa * (double)sb;
        satot += sa; sbtot += sb;
    }
    const double dall = (double)satot * (double)sbtot;

    const double dsame_t = block_reduce(dsame, red, t2);
    const double dall_t  = block_reduce(dall,  red, t2);
    const double sq0_t   = block_reduce((double)v0 * v0, red, t2);
    const double sqN_t   = block_reduce((double)vN * vN, red, t2);

    if (t2 == 0) {
        double term12 = 0.0;
        #pragma unroll
        for (int l = 0; l < NCLS; l++) {
            double sqA = (double)Qs[l] - ((l == lastL)  ? sqN_t : 0.0);
            double sqB = (double)Qs[l] - ((l == firstL) ? sq0_t : 0.0);
            double cA  = (double)(Cs[l] - ((l == lastL)  ? 1 : 0));
            double cB  = (double)(Cs[l] - ((l == firstL) ? 1 : 0));
            term12 += sqA * (2.0 * cB - (double)(N - 1))
                    + sqB * (2.0 * cA - (double)(N - 1));
        }
        double result = term12 - 2.0 * (2.0 * dsame_t - dall_t);
        const double PAR = 0.5 / (double)N;   // COV * 0.5 / BATCH_SIZE
        res[0] = (float)(PAR * result);
    }

    // Re-zero accumulators for the next graph replay (after all reads).
    __syncthreads();
    for (int i = t2; i < SDIM; i += 256) g_S[i] = 0.f;
    if (t2 < NCLS) { g_Q[t2] = 0.f; g_C[t2] = 0; }
    if (t2 == 0)   g_ctr = 0;
}

extern "C" void kernel_launch(void* const* d_in, const int* in_sizes, int n_in,
                              void* d_out, int out_size) {
    const float* x   = (const float*)d_in[0];
    const int*   lab = (const int*)d_in[1];
    float*       res = (float*)d_out;
    (void)in_sizes; (void)n_in; (void)out_size;

    k_all<<<NB, 256>>>(x, lab, res);
}

// round 7
// speedup vs baseline: 1.2257x; 1.2257x over previous
#include <cuda_runtime.h>

#define N     8192
#define D     256
#define D4    64            // D/4
#define NCLS  10
#define NB    128           // accumulate blocks
#define RPB   64            // rows per block
#define SG    4             // subgroups (64 threads each)
#define RPT   8             // rows per subgroup per tile
#define TILES 2
#define SDIM  (NCLS * D)    // 2560
#define SDIM4 (NCLS * D4)   // 640
#define K2B   11            // K2 grid

// Scratch: partials fully overwritten every replay; g_ctr reset by last block.
__device__ float g_partS[NB][SDIM];   // 1.28 MB
__device__ float g_partQ[NB][NCLS];
__device__ float g_S[SDIM];
__device__ float g_Qg[NCLS];
__device__ int   g_Cg[NCLS];
__device__ int   g_ctr;

// ---------------------------------------------------------------------------
// K1: stream 8 MB input once. 4 subgroups x 64 threads; subgroup handles 8
// rows per tile, 2 tiles. Labels are uniform across a subgroup per row ->
// warp-uniform branch tree touches exactly one class accumulator per row.
// ---------------------------------------------------------------------------
__global__ void __launch_bounds__(256) k_accum(const float* __restrict__ x,
                                               const int* __restrict__ lab) {
    __shared__ float4 Ssh[SG][SDIM4];    // 40 KB
    __shared__ float  qred[8][NCLS];
    __shared__ int    labs[RPB];

    const int tid = threadIdx.x;
    const int g   = tid >> 6;            // subgroup 0..3
    const int t   = tid & 63;            // dim-group 0..63
    const int b   = blockIdx.x;

    if (tid < RPB) labs[tid] = lab[b * RPB + tid];
    __syncthreads();

    float4 S[NCLS];
    float  Q[NCLS];
    #pragma unroll
    for (int k = 0; k < NCLS; k++) {
        S[k] = make_float4(0.f, 0.f, 0.f, 0.f);
        Q[k] = 0.f;
    }

    const float4* __restrict__ p =
        reinterpret_cast<const float4*>(x) + (size_t)(b * RPB + g * RPT) * D4 + t;

#define BODY(k) { S[k].x += v[r].x; S[k].y += v[r].y;                          \
                  S[k].z += v[r].z; S[k].w += v[r].w; Q[k] += q; }
    #pragma unroll
    for (int tile = 0; tile < TILES; tile++) {
        // Front-batch 8 row loads (high MLP), then branch on uniform label.
        float4 v[RPT];
        #pragma unroll
        for (int r = 0; r < RPT; r++) v[r] = p[(tile * 32 + r) * D4];
        #pragma unroll
        for (int r = 0; r < RPT; r++) {
            const int l = labs[tile * 32 + g * RPT + r];
            float q = v[r].x * v[r].x;
            q = fmaf(v[r].y, v[r].y, q);
            q = fmaf(v[r].z, v[r].z, q);
            q = fmaf(v[r].w, v[r].w, q);
            if      (l == 0) BODY(0)
            else if (l == 1) BODY(1)
            else if (l == 2) BODY(2)
            else if (l == 3) BODY(3)
            else if (l == 4) BODY(4)
            else if (l == 5) BODY(5)
            else if (l == 6) BODY(6)
            else if (l == 7) BODY(7)
            else if (l == 8) BODY(8)
            else             BODY(9)
        }
    }
#undef BODY

    // Subgroups dump to private buffers (parallel, conflict-free).
    #pragma unroll
    for (int k = 0; k < NCLS; k++) Ssh[g][k * D4 + t] = S[k];
    __syncthreads();

    // Cooperative 4-way merge -> one STG.128 stream (no atomics).
    float4* dst = reinterpret_cast<float4*>(g_partS[b]);
    #pragma unroll
    for (int i = tid; i < SDIM4; i += 256) {
        float4 a = Ssh[0][i], b1 = Ssh[1][i], c = Ssh[2][i], d = Ssh[3][i];
        a.x += b1.x; a.y += b1.y; a.z += b1.z; a.w += b1.w;
        c.x += d.x;  c.y += d.y;  c.z += d.z;  c.w += d.w;
        a.x += c.x;  a.y += c.y;  a.z += c.z;  a.w += c.w;
        dst[i] = a;
    }

    // Q: shfl-reduce per warp, then threads 0..9 sum the 8 warps.
    const int lane = tid & 31, w = tid >> 5;
    #pragma unroll
    for (int k = 0; k < NCLS; k++) {
        float vq = Q[k];
        #pragma unroll
        for (int off = 16; off; off >>= 1)
            vq += __shfl_down_sync(0xffffffffu, vq, off);
        if (lane == 0) qred[w][k] = vq;
    }
    __syncthreads();
    if (tid < NCLS) {
        float s = 0.f;
        #pragma unroll
        for (int w2 = 0; w2 < 8; w2++) s += qred[w2][tid];
        g_partQ[b][tid] = s;
    }
}

// ---------------------------------------------------------------------------
// K2: 11 blocks. Blocks 0..9 reduce S partials (128 each, independent L2-hot
// loads). Block 10 reduces Q and computes class counts from labels. Last
// block (election over 11) runs the epilogue and resets the counter.
// ---------------------------------------------------------------------------
__device__ __forceinline__ double block_reduce(double v, double* red, int t) {
    __syncthreads();
    red[t] = v;
    __syncthreads();
    #pragma unroll
    for (int s2 = 128; s2; s2 >>= 1) {
        if (t < s2) red[t] += red[t + s2];
        __syncthreads();
    }
    return red[0];
}

__global__ void __launch_bounds__(256) k_fin(const float* __restrict__ x,
                                             const int* __restrict__ lab,
                                             float* __restrict__ res) {
    const int bx  = blockIdx.x;
    const int tid = threadIdx.x;

    if (bx < 10) {
        const int gid = bx * 256 + tid;          // 0..2559
        float a0 = 0.f, a1 = 0.f, a2 = 0.f, a3 = 0.f;
        #pragma unroll
        for (int i = 0; i < NB; i += 4) {
            a0 += g_partS[i + 0][gid];
            a1 += g_partS[i + 1][gid];
            a2 += g_partS[i + 2][gid];
            a3 += g_partS[i + 3][gid];
        }
        g_S[gid] = (a0 + a1) + (a2 + a3);
    } else {
        // Q: 160 threads, each sums 8 partials of one class.
        __shared__ float qpart[160];
        __shared__ int   cnt[NCLS];
        if (tid < 160) {
            const int l = tid >> 4, i0 = (tid & 15) * 8;
            float s = 0.f;
            #pragma unroll
            for (int i = 0; i < 8; i++) s += g_partQ[i0 + i][l];
            qpart[tid] = s;
        }
        if (tid < NCLS) cnt[tid] = 0;
        __syncthreads();
        if (tid < NCLS) {
            float s = 0.f;
            #pragma unroll
            for (int j = 0; j < 16; j++) s += qpart[tid * 16 + j];
            g_Qg[tid] = s;
        }
        // Class counts straight from labels (L2-hot, 32 loads/thread).
        int c[NCLS];
        #pragma unroll
        for (int k = 0; k < NCLS; k++) c[k] = 0;
        for (int i = tid; i < N; i += 256) {
            int l = lab[i];
            #pragma unroll
            for (int k = 0; k < NCLS; k++) c[k] += (l == k) ? 1 : 0;
        }
        #pragma unroll
        for (int k = 0; k < NCLS; k++) {
            int v = c[k];
            #pragma unroll
            for (int off = 16; off; off >>= 1)
                v += __shfl_down_sync(0xffffffffu, v, off);
            if ((tid & 31) == 0) atomicAdd(&cnt[k], v);
        }
        __syncthreads();
        if (tid < NCLS) g_Cg[tid] = cnt[tid];
    }

    // ---- Last-block election over 11 blocks ----
    __shared__ int isLast;
    __threadfence();
    __syncthreads();
    if (tid == 0) {
        int prev = atomicAdd(&g_ctr, 1);
        isLast = (prev == K2B - 1) ? 1 : 0;
    }
    __syncthreads();
    if (!isLast) return;
    __threadfence();   // acquire

    // ---------------- Epilogue (thread t = dim t) --------------------------
    __shared__ double red[256];
    __shared__ float  Qs[NCLS];
    __shared__ int    Cs[NCLS];

    const int t = tid;
    if (t < NCLS) { Qs[t] = g_Qg[t]; Cs[t] = g_Cg[t]; }
    const int firstL = lab[0];
    const int lastL  = lab[N - 1];
    const float v0 = x[t];
    const float vN = x[(size_t)(N - 1) * D + t];
    __syncthreads();

    double dsame = 0.0;
    float satot = 0.f, sbtot = 0.f;
    #pragma unroll
    for (int l = 0; l < NCLS; l++) {
        float sv = g_S[l * D + t];
        float sa = sv - ((l == lastL)  ? vN : 0.f);   // rows i in [0, N-1)
        float sb = sv - ((l == firstL) ? v0 : 0.f);   // cols j in [1, N)
        dsame += (double)sa * (double)sb;
        satot += sa; sbtot += sb;
    }
    const double dall = (double)satot * (double)sbtot;

    const double dsame_t = block_reduce(dsame, red, t);
    const double dall_t  = block_reduce(dall,  red, t);
    const double sq0_t   = block_reduce((double)v0 * v0, red, t);
    const double sqN_t   = block_reduce((double)vN * vN, red, t);

    if (t == 0) {
        double term12 = 0.0;
        #pragma unroll
        for (int l = 0; l < NCLS; l++) {
            double sqA = (double)Qs[l] - ((l == lastL)  ? sqN_t : 0.0);
            double sqB = (double)Qs[l] - ((l == firstL) ? sq0_t : 0.0);
            double cA  = (double)(Cs[l] - ((l == lastL)  ? 1 : 0));
            double cB  = (double)(Cs[l] - ((l == firstL) ? 1 : 0));
            term12 += sqA * (2.0 * cB - (double)(N - 1))
                    + sqB * (2.0 * cA - (double)(N - 1));
        }
        double result = term12 - 2.0 * (2.0 * dsame_t - dall_t);
        const double PAR = 0.5 / (double)N;   // COV * 0.5 / BATCH_SIZE
        res[0] = (float)(PAR * result);
        g_ctr = 0;                            // reset for next replay
    }
}

extern "C" void kernel_launch(void* const* d_in, const int* in_sizes, int n_in,
                              void* d_out, int out_size) {
    const float* x   = (const float*)d_in[0];
    const int*   lab = (const int*)d_in[1];
    float*       res = (float*)d_out;
    (void)in_sizes; (void)n_in; (void)out_size;

    k_accum<<<NB, 256>>>(x, lab);
    k_fin<<<K2B, 256>>>(x, lab, res);
}

// round 9
// speedup vs baseline: 1.2570x; 1.0256x over previous
#include <cuda_runtime.h>

#define N     8192
#define D     256
#define D4    64            // D/4
#define NCLS  10
#define NB    128           // accumulate blocks / partial count
#define RPB   64            // rows per block
#define SG    4             // subgroups (64 threads each)
#define RPT   8             // rows per subgroup per tile
#define TILES 2
#define SDIM  (NCLS * D)    // 2560
#define SDIM4 (NCLS * D4)   // 640
#define K2B   81            // 80 S-reduce blocks + 1 Q/count block

// Scratch: partials fully overwritten every replay; g_ctr reset by last block.
__device__ float g_partS[NB][SDIM];   // 1.28 MB
__device__ float g_partQ[NB][NCLS];
__device__ float g_S[SDIM];
__device__ float g_Qg[NCLS];
__device__ int   g_Cg[NCLS];
__device__ int   g_ctr;

// ---------------------------------------------------------------------------
// K1 (unchanged from R7): stream 8 MB input once; warp-uniform branch tree.
// ---------------------------------------------------------------------------
__global__ void __launch_bounds__(256) k_accum(const float* __restrict__ x,
                                               const int* __restrict__ lab) {
    __shared__ float4 Ssh[SG][SDIM4];    // 40 KB
    __shared__ float  qred[8][NCLS];
    __shared__ int    labs[RPB];

    const int tid = threadIdx.x;
    const int g   = tid >> 6;
    const int t   = tid & 63;
    const int b   = blockIdx.x;

    if (tid < RPB) labs[tid] = lab[b * RPB + tid];
    __syncthreads();

    float4 S[NCLS];
    float  Q[NCLS];
    #pragma unroll
    for (int k = 0; k < NCLS; k++) {
        S[k] = make_float4(0.f, 0.f, 0.f, 0.f);
        Q[k] = 0.f;
    }

    const float4* __restrict__ p =
        reinterpret_cast<const float4*>(x) + (size_t)(b * RPB + g * RPT) * D4 + t;

#define BODY(k) { S[k].x += v[r].x; S[k].y += v[r].y;                          \
                  S[k].z += v[r].z; S[k].w += v[r].w; Q[k] += q; }
    #pragma unroll
    for (int tile = 0; tile < TILES; tile++) {
        float4 v[RPT];
        #pragma unroll
        for (int r = 0; r < RPT; r++) v[r] = p[(tile * 32 + r) * D4];
        #pragma unroll
        for (int r = 0; r < RPT; r++) {
            const int l = labs[tile * 32 + g * RPT + r];
            float q = v[r].x * v[r].x;
            q = fmaf(v[r].y, v[r].y, q);
            q = fmaf(v[r].z, v[r].z, q);
            q = fmaf(v[r].w, v[r].w, q);
            if      (l == 0) BODY(0)
            else if (l == 1) BODY(1)
            else if (l == 2) BODY(2)
            else if (l == 3) BODY(3)
            else if (l == 4) BODY(4)
            else if (l == 5) BODY(5)
            else if (l == 6) BODY(6)
            else if (l == 7) BODY(7)
            else if (l == 8) BODY(8)
            else             BODY(9)
        }
    }
#undef BODY

    #pragma unroll
    for (int k = 0; k < NCLS; k++) Ssh[g][k * D4 + t] = S[k];
    __syncthreads();

    float4* dst = reinterpret_cast<float4*>(g_partS[b]);
    #pragma unroll
    for (int i = tid; i < SDIM4; i += 256) {
        float4 a = Ssh[0][i], b1 = Ssh[1][i], c = Ssh[2][i], d = Ssh[3][i];
        a.x += b1.x; a.y += b1.y; a.z += b1.z; a.w += b1.w;
        c.x += d.x;  c.y += d.y;  c.z += d.z;  c.w += d.w;
        a.x += c.x;  a.y += c.y;  a.z += c.z;  a.w += c.w;
        dst[i] = a;
    }

    const int lane = tid & 31, w = tid >> 5;
    #pragma unroll
    for (int k = 0; k < NCLS; k++) {
        float vq = Q[k];
        #pragma unroll
        for (int off = 16; off; off >>= 1)
            vq += __shfl_down_sync(0xffffffffu, vq, off);
        if (lane == 0) qred[w][k] = vq;
    }
    __syncthreads();
    if (tid < NCLS) {
        float s = 0.f;
        #pragma unroll
        for (int w2 = 0; w2 < 8; w2++) s += qred[w2][tid];
        g_partQ[b][tid] = s;
    }
}

// ---------------------------------------------------------------------------
// K2: latency-minimal reduce. Blocks 0..79: 32 outputs/block, 8 threads per
// output; each thread front-batches 16 independent loads, then 3 shfl steps.
// Block 80: Q reduce + class counts. Last of 81 blocks runs the epilogue.
// ---------------------------------------------------------------------------
__device__ __forceinline__ double block_reduce(double v, double* red, int t) {
    __syncthreads();
    red[t] = v;
    __syncthreads();
    #pragma unroll
    for (int s2 = 128; s2; s2 >>= 1) {
        if (t < s2) red[t] += red[t + s2];
        __syncthreads();
    }
    return red[0];
}

__global__ void __launch_bounds__(256) k_fin(const float* __restrict__ x,
                                             const int* __restrict__ lab,
                                             float* __restrict__ res) {
    const int bx  = blockIdx.x;
    const int tid = threadIdx.x;

    if (bx < 80) {
        // Warp w handles outputs [bx*32 + w*4, +4). lane = j*4 + out_sub,
        // j in 0..7 selects a 16-partial chunk.
        const int w       = tid >> 5;
        const int lane    = tid & 31;
        const int out_sub = lane & 3;
        const int j       = lane >> 2;
        const int gid     = bx * 32 + w * 4 + out_sub;
        const int i0      = j * 16;

        // 16 independent loads, all issued before any use.
        float v[16];
        #pragma unroll
        for (int i = 0; i < 16; i++) v[i] = g_partS[i0 + i][gid];

        float s = ((v[0] + v[1]) + (v[2] + v[3])) +
                  ((v[4] + v[5]) + (v[6] + v[7])) +
                  ((v[8] + v[9]) + (v[10] + v[11])) +
                  ((v[12] + v[13]) + (v[14] + v[15]));
        // Reduce over j (lanes stride 4): off = 16, 8, 4.
        s += __shfl_down_sync(0xffffffffu, s, 16);
        s += __shfl_down_sync(0xffffffffu, s, 8);
        s += __shfl_down_sync(0xffffffffu, s, 4);
        if (lane < 4) g_S[bx * 32 + w * 4 + lane] = s;
    } else {
        // Q: 160 threads, class l = tid>>4, chunk of 8 partials each.
        __shared__ float qpart[160];
        __shared__ int   cnt[NCLS];
        if (tid < 160) {
            const int l = tid >> 4, i0 = (tid & 15) * 8;
            float v[8];
            #pragma unroll
            for (int i = 0; i < 8; i++) v[i] = g_partQ[i0 + i][l];
            qpart[tid] = ((v[0] + v[1]) + (v[2] + v[3])) +
                         ((v[4] + v[5]) + (v[6] + v[7]));
        }
        if (tid < NCLS) cnt[tid] = 0;
        __syncthreads();
        if (tid < NCLS) {
            float s = 0.f;
            #pragma unroll
            for (int jj = 0; jj < 16; jj++) s += qpart[tid * 16 + jj];
            g_Qg[tid] = s;
        }
        // Class counts from labels (32 loads/thread, front-batch-ish).
        int c[NCLS];
        #pragma unroll
        for (int k = 0; k < NCLS; k++) c[k] = 0;
        for (int i = tid; i < N; i += 256) {
            int l = lab[i];
            #pragma unroll
            for (int k = 0; k < NCLS; k++) c[k] += (l == k) ? 1 : 0;
        }
        #pragma unroll
        for (int k = 0; k < NCLS; k++) {
            int v = c[k];
            #pragma unroll
            for (int off = 16; off; off >>= 1)
                v += __shfl_down_sync(0xffffffffu, v, off);
            if ((tid & 31) == 0) atomicAdd(&cnt[k], v);
        }
        __syncthreads();
        if (tid < NCLS) g_Cg[tid] = cnt[tid];
    }

    // ---- Last-block election over 81 blocks ----
    __shared__ int isLast;
    __threadfence();
    __syncthreads();
    if (tid == 0) {
        int prev = atomicAdd(&g_ctr, 1);
        isLast = (prev == K2B - 1) ? 1 : 0;
    }
    __syncthreads();
    if (!isLast) return;
    __threadfence();   // acquire

    // ---------------- Epilogue (thread t = dim t) --------------------------
    __shared__ double red[256];
    __shared__ float  Qs[NCLS];
    __shared__ int    Cs[NCLS];

    const int t = tid;
    if (t < NCLS) { Qs[t] = g_Qg[t]; Cs[t] = g_Cg[t]; }
    const int firstL = lab[0];
    const int lastL  = lab[N - 1];
    const float v0 = x[t];
    const float vN = x[(size_t)(N - 1) * D + t];

    // Front-batch the 10 g_S loads.
    float sv[NCLS];
    #pragma unroll
    for (int l = 0; l < NCLS; l++) sv[l] = g_S[l * D + t];
    __syncthreads();

    double dsame = 0.0;
    float satot = 0.f, sbtot = 0.f;
    #pragma unroll
    for (int l = 0; l < NCLS; l++) {
        float sa = sv[l] - ((l == lastL)  ? vN : 0.f);   // rows i in [0, N-1)
        float sb = sv[l] - ((l == firstL) ? v0 : 0.f);   // cols j in [1, N)
        dsame += (double)sa * (double)sb;
        satot += sa; sbtot += sb;
    }
    const double dall = (double)satot * (double)sbtot;

    const double dsame_t = block_reduce(dsame, red, t);
    const double dall_t  = block_reduce(dall,  red, t);
    const double sq0_t   = block_reduce((double)v0 * v0, red, t);
    const double sqN_t   = block_reduce((double)vN * vN, red, t);

    if (t == 0) {
        double term12 = 0.0;
        #pragma unroll
        for (int l = 0; l < NCLS; l++) {
            double sqA = (double)Qs[l] - ((l == lastL)  ? sqN_t : 0.0);
            double sqB = (double)Qs[l] - ((l == firstL) ? sq0_t : 0.0);
            double cA  = (double)(Cs[l] - ((l == lastL)  ? 1 : 0));
            double cB  = (double)(Cs[l] - ((l == firstL) ? 1 : 0));
            term12 += sqA * (2.0 * cB - (double)(N - 1))
                    + sqB * (2.0 * cA - (double)(N - 1));
        }
        double result = term12 - 2.0 * (2.0 * dsame_t - dall_t);
        const double PAR = 0.5 / (double)N;   // COV * 0.5 / BATCH_SIZE
        res[0] = (float)(PAR * result);
        g_ctr = 0;                            // reset for next replay
    }
}

extern "C" void kernel_launch(void* const* d_in, const int* in_sizes, int n_in,
                              void* d_out, int out_size) {
    const float* x   = (const float*)d_in[0];
    const int*   lab = (const int*)d_in[1];
    float*       res = (float*)d_out;
    (void)in_sizes; (void)n_in; (void)out_size;

    k_accum<<<NB, 256>>>(x, lab);
    k_fin<<<K2B, 256>>>(x, lab, res);
}